// round 17
// baseline (speedup 1.0000x reference)
#include <cuda_runtime.h>
#include <cuda_fp16.h>
#include <math.h>
#include <stdint.h>
#include <string.h>

#define Bsz   8192
#define HID   1024
#define NH    16
#define DH    64
#define TOPK  8

// =================== scratch (device globals; no allocs) ====================
__device__ __half g_Hh[(size_t)Bsz * HID];
__device__ __half g_Qh[(size_t)Bsz * HID];
__device__ __half g_Th[(size_t)Bsz * NH * HID];
__device__ __half g_MOh[(size_t)Bsz * HID];
__device__ __half g_GLh[(size_t)Bsz * HID];
__device__ float  g_GLp[(size_t)Bsz * HID];     // gate first-half fp32 partial

__device__ __half g_Wq_h[HID*HID];
__device__ __half g_Wk_h[HID*HID];
__device__ __half g_Wv_h[HID*HID];
__device__ __half g_Wo_h[HID*HID];
__device__ __half g_Wg_h[2*HID*HID];

// =================== helpers =================================================
__device__ __forceinline__ uint32_t smem_u32(const void* p) {
    uint32_t a;
    asm("{ .reg .u64 t; cvta.to.shared.u64 t, %1; cvt.u32.u64 %0, t; }" : "=r"(a) : "l"(p));
    return a;
}
__device__ __forceinline__ void ldsm_x4(uint32_t (&r)[4], uint32_t addr) {
    asm volatile("ldmatrix.sync.aligned.m8n8.x4.shared.b16 {%0,%1,%2,%3}, [%4];"
                 : "=r"(r[0]), "=r"(r[1]), "=r"(r[2]), "=r"(r[3]) : "r"(addr));
}
__device__ __forceinline__ void ldsm_x2(uint32_t (&r)[2], uint32_t addr) {
    asm volatile("ldmatrix.sync.aligned.m8n8.x2.shared.b16 {%0,%1}, [%2];"
                 : "=r"(r[0]), "=r"(r[1]) : "r"(addr));
}
__device__ __forceinline__ void mma16816(float (&d)[4], const uint32_t (&a)[4],
                                         uint32_t b0, uint32_t b1) {
    asm volatile(
        "mma.sync.aligned.m16n8k16.row.col.f32.f16.f16.f32 "
        "{%0,%1,%2,%3}, {%4,%5,%6,%7}, {%8,%9}, {%0,%1,%2,%3};"
        : "+f"(d[0]), "+f"(d[1]), "+f"(d[2]), "+f"(d[3])
        : "r"(a[0]), "r"(a[1]), "r"(a[2]), "r"(a[3]), "r"(b0), "r"(b1));
}
__device__ __forceinline__ void cpa16(uint32_t s, const void* g) {
    asm volatile("cp.async.cg.shared.global [%0], [%1], 16;" :: "r"(s), "l"(g));
}
#define CP_COMMIT() asm volatile("cp.async.commit_group;" ::: "memory")

typedef unsigned long long u64t;
__device__ __forceinline__ u64t f2u(float2 f) { u64t u; memcpy(&u, &f, 8); return u; }
__device__ __forceinline__ float2 u2f(u64t u) { float2 f; memcpy(&f, &u, 8); return f; }
__device__ __forceinline__ void fma2(u64t& d, u64t a, u64t b) {
    asm("fma.rn.f32x2 %0, %1, %2, %0;" : "+l"(d) : "l"(a), "l"(b));
}

// =================== fused conversion kernel ================================
__global__ void __launch_bounds__(256)
conv_all(const float* __restrict__ hidden,
         const float* __restrict__ Wq, const float* __restrict__ Wk,
         const float* __restrict__ Wv, const float* __restrict__ Wo,
         const float* __restrict__ Wg,
         __half* __restrict__ Hh, __half* __restrict__ oq,
         __half* __restrict__ ok, __half* __restrict__ ov,
         __half* __restrict__ oo, __half* __restrict__ og)
{
    __shared__ float tile[32][33];
    int bid = blockIdx.x;
    if (bid < 8192) {
        int idx = bid * 256 + threadIdx.x;
        float4 v = reinterpret_cast<const float4*>(hidden)[idx];
        reinterpret_cast<__half2*>(Hh)[idx*2+0] = __floats2half2_rn(v.x, v.y);
        reinterpret_cast<__half2*>(Hh)[idx*2+1] = __floats2half2_rn(v.z, v.w);
        return;
    }
    if (bid < 12288) {
        int idx = (bid - 8192) * 256 + threadIdx.x;
        int d = idx & 63, j = (idx >> 6) & 1023, h = idx >> 16;
        ok[idx] = __float2half_rn(Wk[(long)j * HID + h * DH + d]);
        return;
    }
    bid -= 12288;
    const float* W; __half* out; int K;
    if (bid < 1024)      { W = Wq; out = oq; K = 1024; }
    else if (bid < 2048) { W = Wv; out = ov; K = 1024; bid -= 1024; }
    else if (bid < 3072) { W = Wo; out = oo; K = 1024; bid -= 2048; }
    else                 { W = Wg; out = og; K = 2048; bid -= 3072; }
    const int ntk = K >> 5;
    const int k0 = (bid % ntk) * 32, n0 = (bid / ntk) * 32;
    const int tx = threadIdx.x & 31, ty = threadIdx.x >> 5;
    #pragma unroll
    for (int i = 0; i < 4; i++)
        tile[ty + i * 8][tx] = W[(long)(k0 + ty + i * 8) * 1024 + n0 + tx];
    __syncthreads();
    #pragma unroll
    for (int i = 0; i < 4; i++)
        out[(long)(n0 + ty + i * 8) * K + k0 + tx] = __float2half_rn(tile[tx][ty + i * 8]);
}

// =================== persistent multistage HMMA GEMM ========================
// OMODE: 0 = fp32 out, 2 = fp16 out. BIAS adds bias[col]. ADDC adds fp32 Cin.
template<int BN, int OMODE, bool BIAS, int BK, int NST, bool ADDC>
__global__ void __launch_bounds__(256, 2)
gemm_ca(const __half* __restrict__ Ah, const __half* __restrict__ A2h, int Ksplit,
        const __half* __restrict__ Bh, const float* __restrict__ bias,
        const float* __restrict__ Cin,
        float* __restrict__ C, __half* __restrict__ Ch,
        int K, int lda, int ldb, int ldc,
        long sAz, long sBz, long sCz,
        int NBX, int NBY, int n_tiles)
{
    constexpr int BM = 128;
    constexpr int ROWH = (BK == 32) ? 40 : 72;
    constexpr int ROWB = ROWH * 2;
    constexpr int ASZ  = BM * ROWB;
    constexpr int BSZ  = BN * ROWB;
    constexpr int STAGE = ASZ + BSZ;
    constexpr int NATOM = BN / 16;
    constexpr int NP   = NATOM / 2;
    constexpr int CPR = (BK * 2) / 16;
    constexpr int KS  = BK / 16;

    extern __shared__ __align__(16) char smem[];
    const uint32_t us = smem_u32(smem);

    const int tid = threadIdx.x, wid = tid >> 5, lane = tid & 31;
    const int warp_m = wid >> 1, warp_n = wid & 1;
    const int NCH = K / BK;

    const int a_r   = lane & 7;
    const int a_row = warp_m * 32 + ((lane >> 3) & 1) * 8 + a_r;
    const int a_kof = (lane >> 4) * 8;
    const int b_row = warp_n * (BN / 2) + ((lane >> 4) * 8) + a_r;
    const int b_kof = ((lane >> 3) & 1) * 8;
    const int tg = lane >> 2, tr = lane & 3;

    for (int t = blockIdx.x; t < n_tiles; t += gridDim.x) {
        const int bx = t % NBX;
        const int rem = t / NBX;
        const int by = rem % NBY;
        const int bz = rem / NBY;
        const long m0 = (long)by * BM;
        const int  n0 = bx * BN;
        const __half* Ab = Ah + (long)bz * sAz;
        const __half* Bb = Bh + (long)bz * sBz;

        float acc[2][NATOM][4];
        #pragma unroll
        for (int i = 0; i < 2; i++)
            #pragma unroll
            for (int j = 0; j < NATOM; j++)
                #pragma unroll
                for (int q = 0; q < 4; q++) acc[i][j][q] = 0.f;

        auto issue_load = [&](int s, int c) {
            const int k0 = c * BK;
            const __half* pAh = Ab;
            int kk = k0;
            if (A2h != nullptr && k0 >= Ksplit) { pAh = A2h; kk = k0 - Ksplit; }
            const uint32_t base = us + s * STAGE;
            for (int i = tid; i < BM * CPR; i += 256) {
                int row = i / CPR, cc = i % CPR;
                cpa16(base + row * ROWB + cc * 16, pAh + (m0 + row) * (long)lda + kk + cc * 8);
            }
            const uint32_t bb = base + ASZ;
            for (int i = tid; i < BN * CPR; i += 256) {
                int row = i / CPR, cc = i % CPR;
                cpa16(bb + row * ROWB + cc * 16, Bb + (long)(n0 + row) * ldb + k0 + cc * 8);
            }
        };

        auto compute = [&](int s) {
            const uint32_t bA = us + s * STAGE;
            const uint32_t bB = bA + ASZ;
            uint32_t ah[2][4];
            uint32_t bh[2][4];
            #pragma unroll
            for (int ma = 0; ma < 2; ma++)
                ldsm_x4(ah[ma], bA + (uint32_t)((a_row + ma * 16) * ROWB + a_kof * 2));
            ldsm_x4(bh[0], bB + (uint32_t)(b_row * ROWB + b_kof * 2));
            #pragma unroll
            for (int ks = 0; ks < KS; ks++) {
                const int kb = ks * 16;
                #pragma unroll
                for (int np = 0; np < NP; np++) {
                    if (np + 1 < NP) {
                        ldsm_x4(bh[(np + 1) & 1],
                                bB + (uint32_t)((b_row + (np + 1) * 16) * ROWB + (kb + b_kof) * 2));
                    } else if (ks + 1 < KS) {
                        ldsm_x4(bh[(np + 1) & 1],
                                bB + (uint32_t)(b_row * ROWB + (kb + 16 + b_kof) * 2));
                    }
                    const uint32_t* bc = bh[np & 1];
                    #pragma unroll
                    for (int ma = 0; ma < 2; ma++) {
                        mma16816(acc[ma][np*2+0], ah[ma], bc[0], bc[1]);
                        mma16816(acc[ma][np*2+1], ah[ma], bc[2], bc[3]);
                    }
                }
                if (ks + 1 < KS) {
                    #pragma unroll
                    for (int ma = 0; ma < 2; ma++)
                        ldsm_x4(ah[ma], bA + (uint32_t)((a_row + ma * 16) * ROWB
                                                        + (kb + 16 + a_kof) * 2));
                }
            }
        };

        #pragma unroll
        for (int s = 0; s < NST - 1; s++) {
            if (s < NCH) issue_load(s, s);
            CP_COMMIT();
        }
        for (int c = 0; c < NCH; c++) {
            const int s = c % NST;
            asm volatile("cp.async.wait_group %0;" :: "n"(NST - 2) : "memory");
            __syncthreads();
            {
                int cn = c + NST - 1;
                if (cn < NCH) issue_load(cn % NST, cn);
            }
            CP_COMMIT();
            compute(s);
        }
        asm volatile("cp.async.wait_group 0;" ::: "memory");

        #pragma unroll
        for (int ma = 0; ma < 2; ma++) {
            #pragma unroll
            for (int na = 0; na < NATOM; na++) {
                long row = m0 + warp_m * 32 + ma * 16 + tg;
                int  col = n0 + warp_n * (BN / 2) + na * 8 + tr * 2;
                long o0 = row * (long)ldc + col + (long)bz * sCz;
                long o1 = o0 + 8 * (long)ldc;
                float2 v0 = make_float2(acc[ma][na][0], acc[ma][na][1]);
                float2 v1 = make_float2(acc[ma][na][2], acc[ma][na][3]);
                if (BIAS) {
                    float2 bv = *reinterpret_cast<const float2*>(&bias[col]);
                    v0.x += bv.x; v0.y += bv.y;
                    v1.x += bv.x; v1.y += bv.y;
                }
                if (ADDC) {
                    float2 c0 = *reinterpret_cast<const float2*>(&Cin[o0]);
                    float2 c1 = *reinterpret_cast<const float2*>(&Cin[o1]);
                    v0.x += c0.x; v0.y += c0.y;
                    v1.x += c1.x; v1.y += c1.y;
                }
                if (OMODE == 0) {
                    *reinterpret_cast<float2*>(&C[o0]) = v0;
                    *reinterpret_cast<float2*>(&C[o1]) = v1;
                } else {
                    *reinterpret_cast<__half2*>(&Ch[o0]) = __floats2half2_rn(v0.x, v0.y);
                    *reinterpret_cast<__half2*>(&Ch[o1]) = __floats2half2_rn(v1.x, v1.y);
                }
            }
        }
        __syncthreads();
    }
}

// =================== T-GEMM: K=64, cross-tile double buffering ==============
__global__ void __launch_bounds__(256, 2)
gemm_T(const __half* __restrict__ Qh, const __half* __restrict__ Wk,
       __half* __restrict__ Th, int n_tiles)
{
    constexpr int BM = 128, BN = 128;
    constexpr int ROWB = 144;
    constexpr int ASZ  = BM * ROWB;
    constexpr int STAGE = 2 * ASZ;
    constexpr int NP = 4, KS = 4, CPR = 8;

    extern __shared__ __align__(16) char smem[];
    const uint32_t us = smem_u32(smem);

    const int tid = threadIdx.x, wid = tid >> 5, lane = tid & 31;
    const int warp_m = wid >> 1, warp_n = wid & 1;

    const int a_r   = lane & 7;
    const int a_row = warp_m * 32 + ((lane >> 3) & 1) * 8 + a_r;
    const int a_kof = (lane >> 4) * 8;
    const int b_row = warp_n * 64 + ((lane >> 4) * 8) + a_r;
    const int b_kof = ((lane >> 3) & 1) * 8;
    const int tg = lane >> 2, tr = lane & 3;

    auto issue_load = [&](int t, int s) {
        const int bx = t & 7, by = (t >> 3) & 63, bz = t >> 9;
        const long m0 = (long)by * BM;
        const int  n0 = bx * BN;
        const __half* A = Qh + (long)bz * DH;
        const __half* B = Wk + (long)bz * (HID * DH);
        const uint32_t base = us + s * STAGE;
        #pragma unroll
        for (int i = tid; i < BM * CPR; i += 256) {
            int row = i >> 3, cc = i & 7;
            cpa16(base + row * ROWB + cc * 16, A + (m0 + row) * (long)HID + cc * 8);
        }
        const uint32_t bb = base + ASZ;
        #pragma unroll
        for (int i = tid; i < BN * CPR; i += 256) {
            int row = i >> 3, cc = i & 7;
            cpa16(bb + row * ROWB + cc * 16, B + (long)(n0 + row) * DH + cc * 8);
        }
    };

    if (blockIdx.x < n_tiles) issue_load(blockIdx.x, 0);
    CP_COMMIT();

    int s = 0;
    for (int t = blockIdx.x; t < n_tiles; t += gridDim.x) {
        asm volatile("cp.async.wait_group 0;" ::: "memory");
        __syncthreads();
        {
            int tn = t + gridDim.x;
            if (tn < n_tiles) issue_load(tn, s ^ 1);
        }
        CP_COMMIT();

        float acc[2][8][4];
        #pragma unroll
        for (int i = 0; i < 2; i++)
            #pragma unroll
            for (int j = 0; j < 8; j++)
                #pragma unroll
                for (int q = 0; q < 4; q++) acc[i][j][q] = 0.f;

        {
            const uint32_t bA = us + s * STAGE;
            const uint32_t bB = bA + ASZ;
            uint32_t ah[2][4];
            uint32_t bh[2][4];
            #pragma unroll
            for (int ma = 0; ma < 2; ma++)
                ldsm_x4(ah[ma], bA + (uint32_t)((a_row + ma * 16) * ROWB + a_kof * 2));
            ldsm_x4(bh[0], bB + (uint32_t)(b_row * ROWB + b_kof * 2));
            #pragma unroll
            for (int ks = 0; ks < KS; ks++) {
                const int kb = ks * 16;
                #pragma unroll
                for (int np = 0; np < NP; np++) {
                    if (np + 1 < NP) {
                        ldsm_x4(bh[(np + 1) & 1],
                                bB + (uint32_t)((b_row + (np + 1) * 16) * ROWB + (kb + b_kof) * 2));
                    } else if (ks + 1 < KS) {
                        ldsm_x4(bh[(np + 1) & 1],
                                bB + (uint32_t)(b_row * ROWB + (kb + 16 + b_kof) * 2));
                    }
                    const uint32_t* bc = bh[np & 1];
                    #pragma unroll
                    for (int ma = 0; ma < 2; ma++) {
                        mma16816(acc[ma][np*2+0], ah[ma], bc[0], bc[1]);
                        mma16816(acc[ma][np*2+1], ah[ma], bc[2], bc[3]);
                    }
                }
                if (ks + 1 < KS) {
                    #pragma unroll
                    for (int ma = 0; ma < 2; ma++)
                        ldsm_x4(ah[ma], bA + (uint32_t)((a_row + ma * 16) * ROWB
                                                        + (kb + 16 + a_kof) * 2));
                }
            }
        }

        {
            const int bx = t & 7, by = (t >> 3) & 63, bz = t >> 9;
            const long m0 = (long)by * BM;
            const int  n0 = bx * BN;
            #pragma unroll
            for (int ma = 0; ma < 2; ma++) {
                #pragma unroll
                for (int na = 0; na < 8; na++) {
                    long row = m0 + warp_m * 32 + ma * 16 + tg;
                    int  col = n0 + warp_n * 64 + na * 8 + tr * 2;
                    long o0 = row * (long)(NH * HID) + (long)bz * HID + col;
                    long o1 = o0 + 8L * (NH * HID);
                    *reinterpret_cast<__half2*>(&Th[o0]) =
                        __floats2half2_rn(acc[ma][na][0], acc[ma][na][1]);
                    *reinterpret_cast<__half2*>(&Th[o1]) =
                        __floats2half2_rn(acc[ma][na][2], acc[ma][na][3]);
                }
            }
        }
        s ^= 1;
    }
}

// =================== attention glue (HMMA scores, 512 threads) ==============
#define ATTN_SMEM 59264
__global__ void __launch_bounds__(512)
attn_kernel(const float* __restrict__ mk, const float* __restrict__ mv,
            __half* __restrict__ Th)
{
    extern __shared__ __align__(16) char sm[];
    const uint32_t us = smem_u32(sm);
    float*  part   = reinterpret_cast<float*>(sm + 49536);
    float*  sc_s   = reinterpret_cast<float*>(sm + 57728);
    float2* attn_p = reinterpret_cast<float2*>(sm + 58240);

    const int b = blockIdx.x, tid = threadIdx.x;
    const int warp = tid >> 5, lane = tid & 31;
    const long bT = (long)b * NH * HID;

    const __half* Tg = Th + bT;
    #pragma unroll
    for (int i = tid; i < 2048; i += 512) {
        int row = i >> 7, cc = i & 127;
        cpa16(us + row * 2064 + cc * 16, Tg + row * 1024 + cc * 8);
    }
    CP_COMMIT();
    const float* mkg = mk + (long)b * TOPK * HID;
    #pragma unroll
    for (int i = tid; i < 2048; i += 512) {
        int row = i >> 8, cc = i & 255;
        float4 v = *reinterpret_cast<const float4*>(&mkg[row * 1024 + cc * 4]);
        uint2 o;
        __half2 o01 = __floats2half2_rn(v.x, v.y);
        __half2 o23 = __floats2half2_rn(v.z, v.w);
        memcpy(&o.x, &o01, 4);
        memcpy(&o.y, &o23, 4);
        *reinterpret_cast<uint2*>(sm + 33024 + row * 2064 + cc * 8) = o;
    }
    asm volatile("cp.async.wait_group 0;" ::: "memory");
    __syncthreads();

    {
        const int a_row = ((lane >> 3) & 1) * 8 + (lane & 7);
        const int a_kof = (lane >> 4) * 8;
        const int b_r   = lane & 7;
        const int b_k   = ((lane >> 3) & 1) * 8;
        float c[4] = {0.f, 0.f, 0.f, 0.f};
        uint32_t ah[4];
        uint32_t bh[2];
        #pragma unroll
        for (int ks = 0; ks < 4; ks++) {
            const int kb = warp * 64 + ks * 16;
            ldsm_x4(ah, us + (uint32_t)(a_row * 2064 + (kb + a_kof) * 2));
            ldsm_x2(bh, us + (uint32_t)(33024 + b_r * 2064 + (kb + b_k) * 2));
            mma16816(c, ah, bh[0], bh[1]);
        }
        const int tg = lane >> 2, tr = lane & 3;
        part[warp * 128 + tg * 8 + tr * 2]         = c[0];
        part[warp * 128 + tg * 8 + tr * 2 + 1]     = c[1];
        part[warp * 128 + (tg + 8) * 8 + tr * 2]   = c[2];
        part[warp * 128 + (tg + 8) * 8 + tr * 2+1] = c[3];
    }
    __syncthreads();

    if (tid < NH * TOPK) {
        float s = 0.f;
        #pragma unroll
        for (int w = 0; w < 16; w++) s += part[w * 128 + tid];
        sc_s[tid] = s * 0.125f;
    }
    __syncthreads();

    if (tid < NH) {
        float e[TOPK];
        float m = -1e30f;
        #pragma unroll
        for (int k = 0; k < TOPK; k++) m = fmaxf(m, sc_s[tid * 8 + k]);
        float sum = 0.f;
        #pragma unroll
        for (int k = 0; k < TOPK; k++) { e[k] = expf(sc_s[tid * 8 + k] - m); sum += e[k]; }
        float inv = 1.f / sum;
        #pragma unroll
        for (int k = 0; k < TOPK; k++) {
            float a = e[k] * inv;
            attn_p[tid * 8 + k] = make_float2(a, a);
        }
    }
    __syncthreads();

    const int j = tid * 2;
    u64t mp[TOPK];
    #pragma unroll
    for (int k = 0; k < TOPK; k++) {
        float2 v = *reinterpret_cast<const float2*>(&mv[((long)b * TOPK + k) * HID + j]);
        mp[k] = f2u(v);
    }
    #pragma unroll
    for (int h = 0; h < NH; h++) {
        u64t s01 = 0ULL;
        #pragma unroll
        for (int k = 0; k < TOPK; k++) {
            u64t ap = *reinterpret_cast<const u64t*>(&attn_p[h * 8 + k]);
            fma2(s01, ap, mp[k]);
        }
        float2 f01 = u2f(s01);
        __half2 o01 = __floats2half2_rn(f01.x, f01.y);
        *reinterpret_cast<__half2*>(&Th[bT + (long)h * HID + j]) = o01;
    }
}

// =================== fused gate + residual + LayerNorm ======================
__global__ void __launch_bounds__(256)
ln_kernel(const __half* __restrict__ Hh, const __half* __restrict__ moh,
          const __half* __restrict__ glh, const float* __restrict__ ln_g,
          const float* __restrict__ ln_b, float* __restrict__ out)
{
    const int b = blockIdx.x, tid = threadIdx.x;
    const long base = (long)b * HID;

    float aug[4];
    float s = 0.f, sq = 0.f;
    {
        const int j = tid * 4;
        uint2 hv2 = *reinterpret_cast<const uint2*>(&Hh[base + j]);
        uint2 gv2 = *reinterpret_cast<const uint2*>(&glh[base + j]);
        uint2 mh2 = *reinterpret_cast<const uint2*>(&moh[base + j]);
        __half2 h01, h23, g01, g23, m01, m23;
        memcpy(&h01, &hv2.x, 4); memcpy(&h23, &hv2.y, 4);
        memcpy(&g01, &gv2.x, 4); memcpy(&g23, &gv2.y, 4);
        memcpy(&m01, &mh2.x, 4); memcpy(&m23, &mh2.y, 4);
        float hv[4] = { __half2float(h01.x), __half2float(h01.y),
                        __half2float(h23.x), __half2float(h23.y) };
        float gv[4] = { __half2float(g01.x), __half2float(g01.y),
                        __half2float(g23.x), __half2float(g23.y) };
        float mo[4] = { __half2float(m01.x), __half2float(m01.y),
                        __half2float(m23.x), __half2float(m23.y) };
        #pragma unroll
        for (int q = 0; q < 4; q++) {
            float g = 1.f / (1.f + expf(-gv[q]));
            float a = hv[q] + g * mo[q];
            aug[q] = a;
            s += a;
            sq = fmaf(a, a, sq);
        }
    }
    __shared__ float rs[8], rq[8];
    const int warp = tid >> 5, lane = tid & 31;
    #pragma unroll
    for (int off = 16; off; off >>= 1) {
        s  += __shfl_down_sync(0xffffffffu, s,  off);
        sq += __shfl_down_sync(0xffffffffu, sq, off);
    }
    if (lane == 0) { rs[warp] = s; rq[warp] = sq; }
    __syncthreads();
    if (tid == 0) {
        float ts = 0.f, tq = 0.f;
        #pragma unroll
        for (int w = 0; w < 8; w++) { ts += rs[w]; tq += rq[w]; }
        rs[0] = ts; rq[0] = tq;
    }
    __syncthreads();
    const float mean = rs[0] * (1.f / HID);
    const float var  = rq[0] * (1.f / HID) - mean * mean;
    const float inv  = rsqrtf(var + 1e-5f);
    {
        const int j = tid * 4;
        float4 gg = *reinterpret_cast<const float4*>(&ln_g[j]);
        float4 bb = *reinterpret_cast<const float4*>(&ln_b[j]);
        float4 o;
        o.x = (aug[0] - mean) * inv * gg.x + bb.x;
        o.y = (aug[1] - mean) * inv * gg.y + bb.y;
        o.z = (aug[2] - mean) * inv * gg.z + bb.z;
        o.w = (aug[3] - mean) * inv * gg.w + bb.w;
        *reinterpret_cast<float4*>(&out[base + j]) = o;
    }
}

// =================== launch ==================================================
extern "C" void kernel_launch(void* const* d_in, const int* in_sizes, int n_in,
                              void* d_out, int out_size)
{
    const float* hidden = (const float*)d_in[0];
    const float* mk     = (const float*)d_in[1];
    const float* mv     = (const float*)d_in[2];
    const float* Wq     = (const float*)d_in[3];
    const float* Wk     = (const float*)d_in[4];
    const float* Wv     = (const float*)d_in[5];
    const float* Wo     = (const float*)d_in[6];
    const float* Wg     = (const float*)d_in[7];
    const float* bg     = (const float*)d_in[8];
    const float* ln_g   = (const float*)d_in[9];
    const float* ln_b   = (const float*)d_in[10];
    float* out = (float*)d_out;

    static __half *Hh=nullptr,*Qh,*Th,*MOh,*GLh;
    static float *GLp;
    static __half *Wq_h,*Wk_h,*Wv_h,*Wo_h,*Wg_h;
    static cudaStream_t s2;
    static cudaEvent_t ev0, ev1;

    constexpr int SM_F128 = 3 * ((128 + 128) * 144);   // 110592
    constexpr int SM_F64  = 3 * ((128 + 64)  * 144);   //  82944
    constexpr int SM_G1   = 3 * ((128 + 128) * 80);    //  61440 (BK=32, co-resident w/ attn)
    constexpr int SM_TK   = 2 * (2 * 128 * 144);       //  73728
    constexpr int PGRID   = 296;

    if (!Hh) {
        cudaGetSymbolAddress((void**)&Hh, g_Hh);
        cudaGetSymbolAddress((void**)&Qh, g_Qh);
        cudaGetSymbolAddress((void**)&Th, g_Th);
        cudaGetSymbolAddress((void**)&MOh, g_MOh);
        cudaGetSymbolAddress((void**)&GLh, g_GLh);
        cudaGetSymbolAddress((void**)&GLp, g_GLp);
        cudaGetSymbolAddress((void**)&Wq_h, g_Wq_h);
        cudaGetSymbolAddress((void**)&Wk_h, g_Wk_h);
        cudaGetSymbolAddress((void**)&Wv_h, g_Wv_h);
        cudaGetSymbolAddress((void**)&Wo_h, g_Wo_h);
        cudaGetSymbolAddress((void**)&Wg_h, g_Wg_h);
        cudaStreamCreateWithFlags(&s2, cudaStreamNonBlocking);
        cudaEventCreateWithFlags(&ev0, cudaEventDisableTiming);
        cudaEventCreateWithFlags(&ev1, cudaEventDisableTiming);
        cudaFuncSetAttribute((const void*)gemm_ca<128,2,false,64,3,false>,
                             cudaFuncAttributeMaxDynamicSharedMemorySize, SM_F128);
        cudaFuncSetAttribute((const void*)gemm_ca<128,0,false,32,3,false>,
                             cudaFuncAttributeMaxDynamicSharedMemorySize, SM_G1);
        cudaFuncSetAttribute((const void*)gemm_ca<128,2,true,64,3,true>,
                             cudaFuncAttributeMaxDynamicSharedMemorySize, SM_F128);
        cudaFuncSetAttribute((const void*)gemm_T,
                             cudaFuncAttributeMaxDynamicSharedMemorySize, SM_TK);
        cudaFuncSetAttribute((const void*)gemm_ca<64,2,false,64,3,false>,
                             cudaFuncAttributeMaxDynamicSharedMemorySize, SM_F64);
        cudaFuncSetAttribute((const void*)attn_kernel,
                             cudaFuncAttributeMaxDynamicSharedMemorySize, ATTN_SMEM);
    }

    // fused conversions
    conv_all<<<17408, 256>>>(hidden, Wq, Wk, Wv, Wo, Wg,
                             Hh, Wq_h, Wk_h, Wv_h, Wo_h, Wg_h);

    // 1) Q = hidden @ Wq
    gemm_ca<128,2,false,64,3,false><<<PGRID, 256, SM_F128>>>(
        Hh, nullptr, HID, Wq_h, nullptr, nullptr,
        nullptr, Qh, HID, HID, HID, HID, 0, 0, 0,
        8, 64, 512);

    // 2) T = per-head Q @ Wk_c
    gemm_T<<<PGRID, 256, SM_TK>>>(Qh, Wk_h, Th, 8192);

    // ---- fork: gate first half (Hh @ Wg_top) overlaps attn/O/Wo ----
    cudaEventRecord(ev0, 0);
    cudaStreamWaitEvent(s2, ev0, 0);
    gemm_ca<128,0,false,32,3,false><<<PGRID, 256, SM_G1, s2>>>(
        Hh, nullptr, HID, Wg_h, nullptr, nullptr,
        GLp, nullptr, HID, HID, 2*HID, HID, 0, 0, 0,
        8, 64, 512);
    cudaEventRecord(ev1, s2);

    // 3) scores (HMMA) + softmax + value mix (main stream)
    attn_kernel<<<Bsz, 512, ATTN_SMEM>>>(mk, mv, Th);

    // 4) O = MV @ Wv_c
    gemm_ca<64,2,false,64,3,false><<<PGRID, 256, SM_F64>>>(
        Th, nullptr, HID, Wv_h, nullptr, nullptr,
        nullptr, Qh, HID, NH*HID, HID, HID, HID, (long)DH*HID, DH,
        1, 64, 1024);

    // 5) memory_out = O @ Wo
    gemm_ca<128,2,false,64,3,false><<<PGRID, 256, SM_F128>>>(
        Qh, nullptr, HID, Wo_h, nullptr, nullptr,
        nullptr, MOh, HID, HID, HID, HID, 0, 0, 0,
        8, 64, 512);

    // ---- join, then gate second half: GL = MOh @ Wg_bot + GLp + bg ----
    cudaStreamWaitEvent(0, ev1, 0);
    gemm_ca<128,2,true,64,3,true><<<PGRID, 256, SM_F128>>>(
        MOh, nullptr, HID, Wg_h + HID, bg, GLp,
        nullptr, GLh, HID, HID, 2*HID, HID, 0, 0, 0,
        8, 64, 512);

    // 7) gate + residual + LayerNorm
    ln_kernel<<<Bsz, 256>>>(Hh, MOh, GLh, ln_g, ln_b, out);
}